// round 14
// baseline (speedup 1.0000x reference)
#include <cuda_runtime.h>
#include <math.h>

// Problem constants (fixed by reference: IMG=2048, strides 8/16/32, B=2, M=128)
#define L3 65536
#define L4 16384
#define L5 4096
#define LTOT (L3 + L4 + L5)   // 86016
#define NB 2
#define NGT 128

// Fused kernel: 672 blocks x 256 threads, 1 location/thread (256 locs/block).
// Same total warps as the 1344x128 variant (same occupancy/latency hiding)
// but half the CTAs -> lower dispatch overhead. Each block is (batch, level)-
// uniform (boundaries % 256 == 0); block = 1 row at p3, 2 at p4, 4 at p5.
__global__ __launch_bounds__(256) void fcos_fused(
    const float* __restrict__ gt,      // (B, 128, 5)
    const float* __restrict__ p3,      // (B, L3, 4)
    const float* __restrict__ p4,
    const float* __restrict__ p5,
    float* __restrict__ out)           // (B, LTOT, 9)
{
    __shared__ float4 sbox[NGT];                 // {x0,y0,x1,y1} per slot
    __shared__ unsigned long long skey[NGT];     // packed winner key
    __shared__ int swc[4];                       // per-warp shortlist count
    __shared__ float sOut[256 * 9];              // staged output (9216 B)

    const int tid   = threadIdx.x;               // 0..255
    const int w     = tid >> 5;
    const int lane  = tid & 31;
    const int gbase = blockIdx.x * 256;
    const int b     = (gbase >= LTOT) ? 1 : 0;
    const int locb  = gbase - b * LTOT;

    // Level selection — uniform per block.
    float s, lo, hi;
    const float* pred;
    int nshift, off;
    if (locb < L3) {
        s = 8.0f;  lo = 0.0f;   hi = 64.0f;
        pred = p3 + (size_t)b * L3 * 4; nshift = 8; off = 0;          // n=256
    } else if (locb < L3 + L4) {
        s = 16.0f; lo = 64.0f;  hi = 128.0f;
        pred = p4 + (size_t)b * L4 * 4; nshift = 7; off = L3;         // n=128
    } else {
        s = 32.0f; lo = 128.0f; hi = INFINITY;
        pred = p5 + (size_t)b * L5 * 4; nshift = 6; off = L3 + L4;    // n=64
    }
    const int nmask = (1 << nshift) - 1;

    const int l0   = locb - off;             // level-local block start
    const int lidx = l0 + tid;               // this thread's location
    const int row  = lidx >> nshift;
    const int col  = lidx & nmask;
    // Analytic coords: (k+0.5)*2^m exact in fp32 -> bitwise equal to ref.
    const float y = ((float)row + 0.5f) * s;
    const float x = ((float)col + 0.5f) * s;

    // Block y-band (1/2/4 rows).
    const float ylo = ((float)(l0 >> nshift)         + 0.5f) * s;
    const float yhi = ((float)((l0 + 255) >> nshift) + 0.5f) * s;

    // Prediction (LDG.128) — issued before any sync so it overlaps phase 1.
    const float4 p = reinterpret_cast<const float4*>(pred)[lidx];

    // ---- Stage the decode half now (independent of the match) ----
    {
        float* o = sOut + tid * 9;
        o[5] = fmaxf(x - fmaxf(p.x, 0.0f) * s, 0.0f);
        o[6] = fmaxf(y - fmaxf(p.y, 0.0f) * s, 0.0f);
        o[7] = fmaxf(x + fmaxf(p.z, 0.0f) * s, 0.0f);
        o[8] = fmaxf(y + fmaxf(p.w, 0.0f) * s, 0.0f);
    }

    // ---- Phase 1: warps 0..3 build compacted per-warp shortlists ----
    if (tid < NGT) {
        const float* g = gt + ((size_t)(b * NGT + tid)) * 5;
        const float bx0 = g[0], by0 = g[1], bx1 = g[2], by1 = g[3];
        // Valid-center window: x in (max(x0,x1-hi), min(x1,x0+hi)), same in y.
        const float xl = fmaxf(bx0, bx1 - hi), xh = fminf(bx1, bx0 + hi);
        const float yl = fmaxf(by0, by1 - hi), yh = fminf(by1, by0 + hi);
        const bool cand = (xh > xl) && (yh > ylo) && (yl < yhi);
        const unsigned mask = __ballot_sync(0xFFFFFFFFu, cand);
        if (cand) {
            const int slot = (w << 5) + __popc(mask & ((1u << lane) - 1u));
            sbox[slot] = make_float4(bx0, by0, bx1, by1);
            const float mmv = 1e8f - (bx1 - bx0) * (by1 - by0);
            // mm bits (positive float, order-isomorphic) | first-index tie | slot.
            skey[slot] = ((unsigned long long)__float_as_uint(mmv) << 32) |
                         ((unsigned)(NGT - 1 - tid) << 8) | (unsigned)slot;
        }
        if (lane == 0) swc[w] = __popc(mask);
    }
    __syncthreads();

    // ---- Phase 2: scan compacted segments ----
    unsigned long long best = 0ull;
    #pragma unroll
    for (int ws = 0; ws < 4; ++ws) {
        const int cnt  = swc[ws];
        const int base = ws << 5;
        for (int k = 0; k < cnt; ++k) {
            const float4 bx = sbox[base + k];
            const float l  = x - bx.x;
            const float t  = y - bx.y;
            const float r  = bx.z - x;
            const float bt = bx.w - y;
            const float pmin = fminf(fminf(l, t), fminf(r, bt));
            const float pmax = fmaxf(fmaxf(l, t), fmaxf(r, bt));
            if (pmin > 0.0f && pmax > lo && pmax < hi) {
                const unsigned long long key = skey[base + k];
                if (key > best) best = key;
            }
        }
    }

    // ---- Phase 3: stage match outputs (5 floats) ----
    {
        const float inv_s = 1.0f / s;
        float* o = sOut + tid * 9;
        if (best == 0ull) {
            o[0] = o[1] = o[2] = o[3] = -1.0f;
            o[4] = -1.0f;
        } else {
            const float4 bx = sbox[best & 0xFFu];
            const float d0 = (x - bx.x) * inv_s;
            const float d1 = (y - bx.y) * inv_s;
            const float d2 = (bx.z - x) * inv_s;
            const float d3 = (bx.w - y) * inv_s;
            const float lrmin = fminf(d0, d2), lrmax = fmaxf(d0, d2);
            const float tbmin = fminf(d1, d3), tbmax = fmaxf(d1, d3);
            const float ratio = fminf(lrmin, tbmin) /
                                (fmaxf(lrmax, tbmax) + 1e-6f);
            o[0] = d0; o[1] = d1; o[2] = d2; o[3] = d3;
            o[4] = sqrtf(fmaxf(ratio, 0.0f));
        }
    }
    __syncwarp();   // warp-local: each warp copies only its own staged region

    // ---- Phase 4: per-warp coalesced copy of its own 288-float region ----
    // Warp region: sOut[288w .. 288(w+1)) = 72 float4 -> contiguous output.
    {
        const float4* src = reinterpret_cast<const float4*>(sOut + 288 * w);
        float4* dst = reinterpret_cast<float4*>(
            out + ((size_t)b * LTOT + off + l0) * 9 + 288 * w);
        #pragma unroll
        for (int k = 0; k < 2; ++k)
            dst[k * 32 + lane] = src[k * 32 + lane];
        if (lane < 8)
            dst[64 + lane] = src[64 + lane];
    }
}

extern "C" void kernel_launch(void* const* d_in, const int* in_sizes, int n_in,
                              void* d_out, int out_size) {
    const float* gt = (const float*)d_in[3];
    const float* p3 = (const float*)d_in[4];
    const float* p4 = (const float*)d_in[5];
    const float* p5 = (const float*)d_in[6];
    float* out = (float*)d_out;

    const int blocks = NB * LTOT / 256;   // 672
    fcos_fused<<<blocks, 256>>>(gt, p3, p4, p5, out);
}

// round 15
// speedup vs baseline: 1.0072x; 1.0072x over previous
#include <cuda_runtime.h>
#include <math.h>

// Problem constants (fixed by reference: IMG=2048, strides 8/16/32, B=2, M=128)
#define L3 65536
#define L4 16384
#define L5 4096
#define LTOT (L3 + L4 + L5)   // 86016
#define NB 2
#define NGT 128

// Fused kernel: 672 blocks x 128 threads, 2 locations/thread (256 locs/block).
// Each block is (batch, level)-uniform; 256 locs = 1 row at p3, 2 at p4,
// 4 at p5. Phase 1 stores all boxes unconditionally (store does NOT depend
// on the ballot -> shorter pre-barrier chain) plus a 4-byte candidate
// bitmap per warp; phase 2 iterates set bits, recomputing the argmax key
// inline. Decode half pre-staged; single block barrier; warp-local
// coalesced float4 output copy.
__global__ __launch_bounds__(128) void fcos_fused(
    const float* __restrict__ gt,      // (B, 128, 5)
    const float* __restrict__ p3,      // (B, L3, 4)
    const float* __restrict__ p4,
    const float* __restrict__ p5,
    float* __restrict__ out)           // (B, LTOT, 9)
{
    __shared__ float4 sbox[NGT];                 // all 128 boxes (by index j)
    __shared__ unsigned smask[4];                // per-warp candidate bitmap
    __shared__ float sOut[128 * 18];             // staged output (9216 B)

    const int tid   = threadIdx.x;               // 0..127
    const int w     = tid >> 5;
    const int lane  = tid & 31;
    const int gbase = blockIdx.x * 256;
    const int b     = (gbase >= LTOT) ? 1 : 0;
    const int locb  = gbase - b * LTOT;

    // Level selection — uniform per block.
    float s, lo, hi;
    const float* pred;
    int nshift, off;
    if (locb < L3) {
        s = 8.0f;  lo = 0.0f;   hi = 64.0f;
        pred = p3 + (size_t)b * L3 * 4; nshift = 8; off = 0;          // n=256
    } else if (locb < L3 + L4) {
        s = 16.0f; lo = 64.0f;  hi = 128.0f;
        pred = p4 + (size_t)b * L4 * 4; nshift = 7; off = L3;         // n=128
    } else {
        s = 32.0f; lo = 128.0f; hi = INFINITY;
        pred = p5 + (size_t)b * L5 * 4; nshift = 6; off = L3 + L4;    // n=64
    }
    const int nmask = (1 << nshift) - 1;

    const int l0   = locb - off;             // level-local block start
    const int lidx = l0 + 2 * tid;           // this thread's first location
    const int row  = lidx >> nshift;
    const int col  = lidx & nmask;           // 2-aligned -> both in one row
    // Analytic coords: (k+0.5)*2^m exact in fp32 -> bitwise equal to ref.
    const float y  = ((float)row + 0.5f) * s;
    const float xA = ((float)col + 0.5f) * s;
    const float xB = xA + s;

    // Analytic y-band of the whole block (1/2/4 rows).
    const float ylo = ((float)(l0 >> nshift)         + 0.5f) * s;
    const float yhi = ((float)((l0 + 255) >> nshift) + 0.5f) * s;

    // gt load issued first (phase 1 consumes it).
    const float* g = gt + ((size_t)(b * NGT + tid)) * 5;
    const float bx0 = g[0], by0 = g[1], bx1 = g[2], by1 = g[3];

    // Predictions (2 x LDG.128), overlap with phase 1.
    const float4 pA = reinterpret_cast<const float4*>(pred)[lidx];
    const float4 pB = reinterpret_cast<const float4*>(pred)[lidx + 1];

    // ---- Phase 1: unconditional box store + candidate bitmap ----
    // STS does not wait on the ballot -> shortest possible pre-barrier chain.
    sbox[tid] = make_float4(bx0, by0, bx1, by1);
    {
        // Valid-center window: x in (max(x0,x1-hi), min(x1,x0+hi)), same in y.
        const float xl = fmaxf(bx0, bx1 - hi), xh = fminf(bx1, bx0 + hi);
        const float yl = fmaxf(by0, by1 - hi), yh = fminf(by1, by0 + hi);
        const bool cand = (xh > xl) && (yh > ylo) && (yl < yhi);
        const unsigned mask = __ballot_sync(0xFFFFFFFFu, cand);
        if (lane == 0) smask[w] = mask;
    }

    // ---- Stage the decode half while the ballot settles ----
    {
        float* o = sOut + tid * 18;
        o[5]  = fmaxf(xA - fmaxf(pA.x, 0.0f) * s, 0.0f);
        o[6]  = fmaxf(y  - fmaxf(pA.y, 0.0f) * s, 0.0f);
        o[7]  = fmaxf(xA + fmaxf(pA.z, 0.0f) * s, 0.0f);
        o[8]  = fmaxf(y  + fmaxf(pA.w, 0.0f) * s, 0.0f);
        o[14] = fmaxf(xB - fmaxf(pB.x, 0.0f) * s, 0.0f);
        o[15] = fmaxf(y  - fmaxf(pB.y, 0.0f) * s, 0.0f);
        o[16] = fmaxf(xB + fmaxf(pB.z, 0.0f) * s, 0.0f);
        o[17] = fmaxf(y  + fmaxf(pB.w, 0.0f) * s, 0.0f);
    }
    __syncthreads();

    // ---- Phase 2: iterate candidate bits; key recomputed inline ----
    // key = mm_bits<<32 | (127-j): positive-float bits are order-isomorphic,
    // ties in mm resolve to smallest j (first occurrence), matching argmax.
    unsigned long long bestA = 0ull, bestB = 0ull;
    #pragma unroll
    for (int ws = 0; ws < 4; ++ws) {
        unsigned m = smask[ws];
        while (m) {
            const int bit = __ffs(m) - 1;
            m &= m - 1;
            const int j = (ws << 5) + bit;
            const float4 bx = sbox[j];
            const float mmv = 1e8f - (bx.z - bx.x) * (bx.w - bx.y);
            const unsigned long long key =
                ((unsigned long long)__float_as_uint(mmv) << 32) |
                (unsigned)(NGT - 1 - j);
            const float t  = y - bx.y;
            const float bt = bx.w - y;
            const float vmin = fminf(t, bt);
            const float vmax = fmaxf(t, bt);
            {
                const float l = xA - bx.x, r = bx.z - xA;
                const float pmin = fminf(fminf(l, r), vmin);
                const float pmax = fmaxf(fmaxf(l, r), vmax);
                if (pmin > 0.0f && pmax > lo && pmax < hi && key > bestA)
                    bestA = key;
            }
            {
                const float l = xB - bx.x, r = bx.z - xB;
                const float pmin = fminf(fminf(l, r), vmin);
                const float pmax = fmaxf(fmaxf(l, r), vmax);
                if (pmin > 0.0f && pmax > lo && pmax < hi && key > bestB)
                    bestB = key;
            }
        }
    }

    // ---- Phase 3: stage match outputs (5 floats per location) ----
    {
        const float inv_s = 1.0f / s;
        float* o = sOut + tid * 18;
        #pragma unroll
        for (int q = 0; q < 2; ++q, o += 9) {
            const unsigned long long best = q ? bestB : bestA;
            const float x = q ? xB : xA;
            if (best == 0ull) {
                o[0] = o[1] = o[2] = o[3] = -1.0f;
                o[4] = -1.0f;
            } else {
                const float4 bx = sbox[NGT - 1 - (int)(best & 0xFFu)];
                const float d0 = (x - bx.x) * inv_s;
                const float d1 = (y - bx.y) * inv_s;
                const float d2 = (bx.z - x) * inv_s;
                const float d3 = (bx.w - y) * inv_s;
                const float lrmin = fminf(d0, d2), lrmax = fmaxf(d0, d2);
                const float tbmin = fminf(d1, d3), tbmax = fmaxf(d1, d3);
                const float ratio = fminf(lrmin, tbmin) /
                                    (fmaxf(lrmax, tbmax) + 1e-6f);
                o[0] = d0; o[1] = d1; o[2] = d2; o[3] = d3;
                o[4] = sqrtf(fmaxf(ratio, 0.0f));
            }
        }
    }
    __syncwarp();   // warp-local: each warp copies only its own staged region

    // ---- Phase 4: per-warp coalesced copy of its own 576-float region ----
    // 144 float4 per warp: 4 full rounds + one half-warp round.
    {
        const float4* src = reinterpret_cast<const float4*>(sOut + 576 * w);
        float4* dst = reinterpret_cast<float4*>(
            out + ((size_t)b * LTOT + off + l0) * 9 + 576 * w);
        #pragma unroll
        for (int k = 0; k < 4; ++k)
            dst[k * 32 + lane] = src[k * 32 + lane];
        if (lane < 16)
            dst[128 + lane] = src[128 + lane];
    }
}

extern "C" void kernel_launch(void* const* d_in, const int* in_sizes, int n_in,
                              void* d_out, int out_size) {
    const float* gt = (const float*)d_in[3];
    const float* p3 = (const float*)d_in[4];
    const float* p4 = (const float*)d_in[5];
    const float* p5 = (const float*)d_in[6];
    float* out = (float*)d_out;

    const int blocks = NB * LTOT / 256;   // 672
    fcos_fused<<<blocks, 128>>>(gt, p3, p4, p5, out);
}

// round 16
// speedup vs baseline: 1.2903x; 1.2811x over previous
#include <cuda_runtime.h>
#include <math.h>

// Problem constants (fixed by reference: IMG=2048, strides 8/16/32, B=2, M=128)
#define L3 65536
#define L4 16384
#define L5 4096
#define LTOT (L3 + L4 + L5)   // 86016
#define NB 2
#define NGT 128

// Fused kernel: 1344 blocks x 128 threads, 1 location/thread (128 locs/block).
// Each block is (batch, level)-uniform (boundaries % 128 == 0). Block spans:
// p3 = half a row (x-band prune), p4 = 1 row, p5 = 2 rows.
// Phase 1: ballot-compacted shortlist (boxes only — no key array).
// Phase 2: dense scan; argmax key = raw fp32 bits of mm (u32, order-
// isomorphic for positive floats), recomputed inline via mm = 1e8 -
// (l+r)*(t+bt); strict '>' + ascending-j scan order reproduces jnp.argmax
// first-index tie-breaking. Decode half pre-staged before the single
// barrier; warp-local coalesced float4 output copy.
__global__ __launch_bounds__(128) void fcos_fused(
    const float* __restrict__ gt,      // (B, 128, 5)
    const float* __restrict__ p3,      // (B, L3, 4)
    const float* __restrict__ p4,
    const float* __restrict__ p5,
    float* __restrict__ out)           // (B, LTOT, 9)
{
    __shared__ float4 sbox[NGT];                 // compacted candidate boxes
    __shared__ int swc[4];                       // per-warp shortlist count
    __shared__ float sOut[128 * 9];              // staged output (4608 B)

    const int tid   = threadIdx.x;               // 0..127
    const int w     = tid >> 5;
    const int lane  = tid & 31;
    const int gbase = blockIdx.x * 128;
    const int b     = (gbase >= LTOT) ? 1 : 0;
    const int locb  = gbase - b * LTOT;

    // Level selection — uniform per block.
    float s, lo, hi;
    const float* pred;
    int nshift, off;
    if (locb < L3) {
        s = 8.0f;  lo = 0.0f;   hi = 64.0f;
        pred = p3 + (size_t)b * L3 * 4; nshift = 8; off = 0;          // n=256
    } else if (locb < L3 + L4) {
        s = 16.0f; lo = 64.0f;  hi = 128.0f;
        pred = p4 + (size_t)b * L4 * 4; nshift = 7; off = L3;         // n=128
    } else {
        s = 32.0f; lo = 128.0f; hi = INFINITY;
        pred = p5 + (size_t)b * L5 * 4; nshift = 6; off = L3 + L4;    // n=64
    }
    const int nmask = (1 << nshift) - 1;

    const int l0   = locb - off;             // level-local block start
    const int lidx = l0 + tid;               // this thread's location
    const int row  = lidx >> nshift;
    const int col  = lidx & nmask;
    // Analytic coords: (k+0.5)*2^m exact in fp32 -> bitwise equal to ref.
    const float y = ((float)row + 0.5f) * s;
    const float x = ((float)col + 0.5f) * s;

    // Block bands. Rows r0..r1; if single-row block (p3), tight x-band too.
    const int r0 = l0 >> nshift, r1 = (l0 + 127) >> nshift;
    const float ylo = ((float)r0 + 0.5f) * s;
    const float yhi = ((float)r1 + 0.5f) * s;
    float xblo, xbhi;
    if (r0 == r1) {
        xblo = ((float)(l0 & nmask) + 0.5f) * s;
        xbhi = xblo + 127.0f * s;
    } else {
        xblo = -1e30f; xbhi = 1e30f;
    }

    // gt load issued early (phase 1 consumes it).
    const float* g = gt + ((size_t)(b * NGT + tid)) * 5;
    const float bx0 = g[0], by0 = g[1], bx1 = g[2], by1 = g[3];

    // Prediction (LDG.128) — overlaps phase 1.
    const float4 p = reinterpret_cast<const float4*>(pred)[lidx];

    // ---- Stage the decode half now (independent of the match) ----
    {
        float* o = sOut + tid * 9;
        o[5] = fmaxf(x - fmaxf(p.x, 0.0f) * s, 0.0f);
        o[6] = fmaxf(y - fmaxf(p.y, 0.0f) * s, 0.0f);
        o[7] = fmaxf(x + fmaxf(p.z, 0.0f) * s, 0.0f);
        o[8] = fmaxf(y + fmaxf(p.w, 0.0f) * s, 0.0f);
    }

    // ---- Phase 1: 4 warps build compacted per-warp shortlists ----
    {
        // Valid-center window: x in (max(x0,x1-hi), min(x1,x0+hi)), same in y.
        const float xl = fmaxf(bx0, bx1 - hi), xh = fminf(bx1, bx0 + hi);
        const float yl = fmaxf(by0, by1 - hi), yh = fminf(by1, by0 + hi);
        const bool cand = (xh > xl) && (yh > ylo) && (yl < yhi) &&
                          (xl < xbhi) && (xh > xblo);
        const unsigned mask = __ballot_sync(0xFFFFFFFFu, cand);
        if (cand) {
            const int slot = (w << 5) + __popc(mask & ((1u << lane) - 1u));
            sbox[slot] = make_float4(bx0, by0, bx1, by1);
        }
        if (lane == 0) swc[w] = __popc(mask);
    }
    __syncthreads();

    // ---- Phase 2: dense scan; u32 key = fp32 bits of mm, inline ----
    unsigned best = 0u;     // 0 = no match (valid mm bits are ~0x4CBE... > 0)
    int bslot = 0;
    #pragma unroll
    for (int ws = 0; ws < 4; ++ws) {
        const int cnt  = swc[ws];
        const int base = ws << 5;
        for (int k = 0; k < cnt; ++k) {
            const float4 bx = sbox[base + k];
            const float l  = x - bx.x;
            const float t  = y - bx.y;
            const float r  = bx.z - x;
            const float bt = bx.w - y;
            const float pmin = fminf(fminf(l, t), fminf(r, bt));
            const float pmax = fmaxf(fmaxf(l, t), fmaxf(r, bt));
            // mm = 1e8 - (x1-x0)*(y1-y0) = 1e8 - (l+r)*(t+bt), same fp32
            // rounding as the reference (sub, sub, mul, sub ordering kept).
            const float mmv = 1e8f - (bx.z - bx.x) * (bx.w - bx.y);
            const unsigned key = __float_as_uint(mmv);
            if (pmin > 0.0f && pmax > lo && pmax < hi && key > best) {
                best = key; bslot = base + k;
            }
        }
    }

    // ---- Phase 3: stage match outputs (5 floats) ----
    {
        const float inv_s = 1.0f / s;
        float* o = sOut + tid * 9;
        if (best == 0u) {
            o[0] = o[1] = o[2] = o[3] = -1.0f;
            o[4] = -1.0f;
        } else {
            const float4 bx = sbox[bslot];
            const float d0 = (x - bx.x) * inv_s;
            const float d1 = (y - bx.y) * inv_s;
            const float d2 = (bx.z - x) * inv_s;
            const float d3 = (bx.w - y) * inv_s;
            const float lrmin = fminf(d0, d2), lrmax = fmaxf(d0, d2);
            const float tbmin = fminf(d1, d3), tbmax = fmaxf(d1, d3);
            const float ratio = fminf(lrmin, tbmin) /
                                (fmaxf(lrmax, tbmax) + 1e-6f);
            o[0] = d0; o[1] = d1; o[2] = d2; o[3] = d3;
            o[4] = sqrtf(fmaxf(ratio, 0.0f));
        }
    }
    __syncwarp();   // warp-local: each warp copies only its own staged region

    // ---- Phase 4: per-warp coalesced copy of its own 288-float region ----
    // Warp region: sOut[288w .. 288(w+1)) = 72 float4 -> contiguous output.
    {
        const float4* src = reinterpret_cast<const float4*>(sOut + 288 * w);
        float4* dst = reinterpret_cast<float4*>(
            out + ((size_t)b * LTOT + off + l0) * 9 + 288 * w);
        #pragma unroll
        for (int k = 0; k < 2; ++k)
            dst[k * 32 + lane] = src[k * 32 + lane];
        if (lane < 8)
            dst[64 + lane] = src[64 + lane];
    }
}

extern "C" void kernel_launch(void* const* d_in, const int* in_sizes, int n_in,
                              void* d_out, int out_size) {
    const float* gt = (const float*)d_in[3];
    const float* p3 = (const float*)d_in[4];
    const float* p4 = (const float*)d_in[5];
    const float* p5 = (const float*)d_in[6];
    float* out = (float*)d_out;

    const int blocks = NB * LTOT / 128;   // 1344
    fcos_fused<<<blocks, 128>>>(gt, p3, p4, p5, out);
}